// round 17
// baseline (speedup 1.0000x reference)
#include <cuda_runtime.h>
#include <cuda_fp16.h>
#include <math.h>
#include <cstdint>

// ---------------------------------------------------------------- constants
#define NBLK  16
#define LSEQ  2048
#define CKD   32
#define CVD   64
#define NPOSF 32768.0f
#define EPSB  1e-5f
#define SCALE_Q 0.25505654350925196f   // (1/sqrt(32)) * log2(e)
#define NBANK 32
#define NCOVP 32

// per-(nb,kt) staged tile blob: [K fp16 10240 | V fp16 17408]
#define TILE_BYTES 27648
#define BLOB_V     10240

// ---------------------------------------------------------------- scratch
__device__ __half g_xcp[4 * 64 * 8192];      // [n][c][px] fp16
__device__ __half g_xpc[32768 * 64];         // [px][c]    fp16
__device__ float  g_covp[NCOVP * 4096];      // cov partials (overwritten each run)
__device__ __half g_wh[128 * 64];            // fp16 weights: q 0-31, k 32-63, v 64-127
__device__ float  g_aff_a[128], g_aff_c[128];
__device__ __half g_qh[NBLK * LSEQ * CKD];
__device__ __align__(128) unsigned char g_tiles[NBLK * 16 * TILE_BYTES];
__device__ float g_sum[NBANK * 64];          // mean banks; zero at load; attn re-zeroes

// ---------------------------------------------------------------- helpers
__device__ __forceinline__ void mma_f16(float* c, const uint32_t* a,
                                        uint32_t b0, uint32_t b1) {
    asm volatile(
        "mma.sync.aligned.m16n8k16.row.col.f32.f16.f16.f32 "
        "{%0,%1,%2,%3}, {%4,%5,%6,%7}, {%8,%9}, {%0,%1,%2,%3};"
        : "+f"(c[0]), "+f"(c[1]), "+f"(c[2]), "+f"(c[3])
        : "r"(a[0]), "r"(a[1]), "r"(a[2]), "r"(a[3]), "r"(b0), "r"(b1));
}
__device__ __forceinline__ uint32_t pack_f16x2(float lo, float hi) {
    uint32_t r;
    asm("cvt.rn.f16x2.f32 %0, %1, %2;" : "=r"(r) : "f"(hi), "f"(lo));
    return r;
}
__device__ __forceinline__ float ex2(float x) {
    float r;
    asm("ex2.approx.ftz.f32 %0, %1;" : "=f"(r) : "f"(x));
    return r;
}
#define LDSM_X4(r0, r1, r2, r3, addr) \
    asm volatile("ldmatrix.sync.aligned.m8n8.x4.shared.b16 {%0,%1,%2,%3}, [%4];" \
        : "=r"(r0), "=r"(r1), "=r"(r2), "=r"(r3) : "r"(addr))

#define MBARRIER_INIT(mb, cnt) \
    asm volatile("mbarrier.init.shared.b64 [%0], %1;" :: "r"((uint32_t)(mb)), "r"((uint32_t)(cnt)) : "memory")
#define MBARRIER_EXPECT_TX(mb, bytes) \
    asm volatile("mbarrier.arrive.expect_tx.shared.b64 _, [%0], %1;" :: "r"((uint32_t)(mb)), "r"((uint32_t)(bytes)) : "memory")
#define CP_BULK(dst, src, bytes, mbar) \
    asm volatile("cp.async.bulk.shared::cta.global.mbarrier::complete_tx::bytes [%0], [%1], %2, [%3];" \
                 :: "r"((uint32_t)(dst)), "l"(src), "r"((uint32_t)(bytes)), "r"((uint32_t)(mbar)) : "memory")
#define MBARRIER_WAIT_PARITY(mb, par) do {                                          \
    uint32_t _mbar = (uint32_t)(mb); uint32_t _par = (uint32_t)(par); uint32_t _done;\
    asm volatile("{\n\t.reg .pred p;\n\t"                                           \
        "mbarrier.try_wait.parity.acquire.cta.shared::cta.b64 p, [%1], %2;\n\t"     \
        "selp.b32 %0, 1, 0, p;\n\t}" : "=r"(_done) : "r"(_mbar), "r"(_par) : "memory"); \
    if (!_done) {                                                                   \
        asm volatile("{\n\t.reg .pred P1;\n\t"                                      \
            "WAIT_LOOP_%=:\n\t"                                                     \
            "mbarrier.try_wait.parity.acquire.cta.shared::cta.b64 P1, [%0], %1, 0x989680;\n\t" \
            "@P1 bra.uni WAIT_DONE_%=;\n\t"                                         \
            "bra.uni WAIT_LOOP_%=;\n\t"                                             \
            "WAIT_DONE_%=:\n\t}" :: "r"(_mbar), "r"(_par) : "memory");              \
    } } while (0)

__device__ __forceinline__ uint32_t smem_u32(const void* p) {
    uint32_t a;
    asm("{ .reg .u64 t; cvta.to.shared.u64 t, %1; cvt.u32.u64 %0, t; }" : "=r"(a) : "l"(p));
    return a;
}

// ---------------------------------------------------------------- K1: cvt (x -> fp16 both orientations + mean banks)
__global__ __launch_bounds__(256) void cvt_kernel(const float* __restrict__ x) {
    __shared__ __half sT[256 * 66];    // [px][c] pitch 66
    const int ct = blockIdx.x;         // 128
    const int n  = ct >> 5, ch = ct & 31;
    const int px0 = ch * 256;
    const int tid = threadIdx.x;

    const float* xb = x + (size_t)n * 524288 + px0;
    // thread tid owns px j = tid for all 64 channels
    {
        const int j = tid;
#pragma unroll 8
        for (int c = 0; c < 64; c++) {
            __half hv = __float2half(xb[c * 8192 + j]);
            g_xcp[(size_t)n * 524288 + c * 8192 + px0 + j] = hv;
            sT[j * 66 + c] = hv;
        }
    }
    __syncthreads();
    // channel sums for mean
    if (tid < 64) {
        float s = 0.f;
#pragma unroll 8
        for (int j2 = 0; j2 < 256; j2++) s += __half2float(sT[j2 * 66 + tid]);
        atomicAdd(&g_sum[(ct & (NBANK - 1)) * 64 + tid], s);
    }
    // transposed output [px][c]
    for (int f = tid; f < 8192; f += 256) {
        int j2 = f >> 5, cp = f & 31;
        uint32_t u = (uint32_t)__half_as_ushort(sT[j2 * 66 + cp * 2]) |
                     ((uint32_t)__half_as_ushort(sT[j2 * 66 + cp * 2 + 1]) << 16);
        ((uint32_t*)g_xpc)[(size_t)(n * 8192 + px0 + j2) * 32 + cp] = u;
    }
}

// ---------------------------------------------------------------- K2: cov partials (X X^T via HMMA)
__global__ __launch_bounds__(256) void cov_kernel() {
    __shared__ __half sC[64 * 136];    // [c][px128] pitch 272B
    const int ct = blockIdx.x;         // 32
    const int n = ct >> 3, chunk = ct & 7;
    const int px0 = chunk * 1024;
    const int tid = threadIdx.x, wid = tid >> 5, ln = tid & 31;
    const int mb4 = wid & 3, h2 = wid >> 2;
    const int li = ln & 7, tsel = ln >> 3;
    const int qr = ln >> 2, qc = ln & 3;
    const uint32_t sb = smem_u32(sC);

    const uint32_t abase = (uint32_t)((mb4 * 16 + (tsel & 1) * 8 + li) * 272 + (tsel >> 1) * 16);
    const uint32_t bbase = (uint32_t)((h2 * 32 + (tsel >> 1) * 8 + li) * 272 + (tsel & 1) * 16);

    float C[4][4];
#pragma unroll
    for (int j = 0; j < 4; j++)
#pragma unroll
        for (int k = 0; k < 4; k++) C[j][k] = 0.f;

    for (int sc = 0; sc < 8; sc++) {
        __syncthreads();
        for (int f = tid; f < 64 * 16; f += 256) {
            int c = f >> 4, q = f & 15;
            *(uint4*)((char*)sC + c * 272 + q * 16) =
                *((const uint4*)(g_xcp + (size_t)n * 524288 + c * 8192 + px0 + sc * 128) + q);
        }
        __syncthreads();
#pragma unroll
        for (int s = 0; s < 8; s++) {
            uint32_t af[4];
            LDSM_X4(af[0], af[1], af[2], af[3], sb + abase + s * 32);
            uint32_t b0, b1, b2, b3;
            LDSM_X4(b0, b1, b2, b3, sb + bbase + s * 32);
            mma_f16(C[0], af, b0, b1);
            mma_f16(C[1], af, b2, b3);
            LDSM_X4(b0, b1, b2, b3, sb + bbase + 16 * 272 + s * 32);
            mma_f16(C[2], af, b0, b1);
            mma_f16(C[3], af, b2, b3);
        }
    }
    const int c1 = mb4 * 16 + qr;
    float* dst = g_covp + ct * 4096;
#pragma unroll
    for (int j = 0; j < 4; j++) {
        int c2 = h2 * 32 + j * 8 + qc * 2;
        dst[c1 * 64 + c2]           = C[j][0];
        dst[c1 * 64 + c2 + 1]       = C[j][1];
        dst[(c1 + 8) * 64 + c2]     = C[j][2];
        dst[(c1 + 8) * 64 + c2 + 1] = C[j][3];
    }
}

// ---------------------------------------------------------------- K3: fold (analytic BN -> affine, weights fp16)
__global__ __launch_bounds__(256) void fold_kernel(
    const float* __restrict__ Wq, const float* __restrict__ Wk, const float* __restrict__ Wv,
    const float* __restrict__ gq, const float* __restrict__ betaq,
    const float* __restrict__ gk, const float* __restrict__ betak,
    const float* __restrict__ bv)
{
    __shared__ float Cov[64][65];
    __shared__ float mu[64];
    __shared__ float Wsm[64][65];
    const int tid = threadIdx.x, wid = tid >> 5, ln = tid & 31;

    if (tid < 64) {
        float s = 0.f;
#pragma unroll
        for (int b = 0; b < NBANK; b++) s += g_sum[b * 64 + tid];
        mu[tid] = s / NPOSF;
    }
    for (int f = tid; f < 128 * 64; f += 256) {
        int o = f >> 6, c = f & 63;
        float w = (o < 32) ? Wq[o * 64 + c]
                           : ((o < 64) ? Wk[(o - 32) * 64 + c] : Wv[(o - 64) * 64 + c]);
        g_wh[f] = __float2half(w);
        if (o < 64) Wsm[o][c] = w;
    }
    __syncthreads();
    for (int f = tid; f < 4096; f += 256) {
        float s = 0.f;
#pragma unroll 8
        for (int p = 0; p < NCOVP; p++) s += g_covp[p * 4096 + f];
        int c1 = f >> 6, c2 = f & 63;
        Cov[c1][c2] = s / NPOSF - mu[c1] * mu[c2];
    }
    __syncthreads();

#pragma unroll
    for (int oi = 0; oi < 8; oi++) {
        const int oc = wid * 8 + oi;
        float vpart = 0.f, mpart = 0.f;
#pragma unroll
        for (int half = 0; half < 2; half++) {
            int c1 = ln + half * 32;
            float t = 0.f;
#pragma unroll 8
            for (int c2 = 0; c2 < 64; c2++) t += Cov[c1][c2] * Wsm[oc][c2];
            vpart += t * Wsm[oc][c1];
            mpart += Wsm[oc][c1] * mu[c1];
        }
#pragma unroll
        for (int off = 16; off > 0; off >>= 1) {
            vpart += __shfl_xor_sync(0xffffffffu, vpart, off);
            mpart += __shfl_xor_sync(0xffffffffu, mpart, off);
        }
        if (ln == 0) {
            float g  = (oc < 32) ? gq[oc]    : gk[oc - 32];
            float be = (oc < 32) ? betaq[oc] : betak[oc - 32];
            float a  = g * rsqrtf(vpart + EPSB);
            float c  = be - a * mpart;
            if (oc < 32) { a *= SCALE_Q; c *= SCALE_Q; }
            g_aff_a[oc] = a;
            g_aff_c[oc] = c;
        }
    }
    if (tid < 64) { g_aff_a[64 + tid] = 1.0f; g_aff_c[64 + tid] = bv[tid]; }
}

// ---------------------------------------------------------------- K4: conv via HMMA -> normalized fp16 q/k/v in final layouts
__global__ __launch_bounds__(256) void convmma_kernel() {
    __shared__ __half sX[128 * 72];    // [t][c] pitch 144B
    __shared__ __half sW[128 * 72];    // [oc][c] pitch 144B
    __shared__ float sA[128], sCc[128];
    const int kt = blockIdx.x, nb = blockIdx.y;
    const int n = nb >> 2, b = nb & 3, bi = b >> 1, bj = b & 1;
    const int tid = threadIdx.x, wid = tid >> 5, ln = tid & 31;
    const int li = ln & 7, tsel = ln >> 3, qr = ln >> 2, qc = ln & 3;

    if (tid < 128) { sA[tid] = g_aff_a[tid]; sCc[tid] = g_aff_c[tid]; }
    for (int f = tid; f < 128 * 8; f += 256) {
        int t = f >> 3, q = f & 7;
        int hl = t >> 6, side = (t >> 5) & 1, wl = t & 31;
        size_t px = (size_t)n * 8192 + (size_t)(bi * 32 + kt * 2 + hl) * 128
                    + side * 64 + bj * 32 + wl;
        *(uint4*)((char*)sX + t * 144 + q * 16) = *((const uint4*)(g_xpc + px * 64) + q);
        *(uint4*)((char*)sW + t * 144 + q * 16) = *((const uint4*)(g_wh + t * 64) + q);
    }
    __syncthreads();
    const uint32_t sbX = smem_u32(sX), sbW = smem_u32(sW);

    // ---- phase A: [128px x 64c] x [64c x 64oc(q,k)] ----
    uint32_t af[4][4];
    const uint32_t abase = (uint32_t)((wid * 16 + (tsel & 1) * 8 + li) * 144 + (tsel >> 1) * 16);
#pragma unroll
    for (int s = 0; s < 4; s++)
        LDSM_X4(af[s][0], af[s][1], af[s][2], af[s][3], sbX + abase + s * 32);

    float Cqk[8][4];
#pragma unroll
    for (int j = 0; j < 8; j++)
#pragma unroll
        for (int k = 0; k < 4; k++) Cqk[j][k] = 0.f;

#pragma unroll
    for (int g = 0; g < 4; g++) {
        const uint32_t bbase = (uint32_t)((g * 16 + (tsel >> 1) * 8 + li) * 144 + (tsel & 1) * 16);
#pragma unroll
        for (int s = 0; s < 4; s++) {
            uint32_t b0, b1, b2, b3;
            LDSM_X4(b0, b1, b2, b3, sbW + bbase + s * 32);
            mma_f16(Cqk[2 * g],     af[s], b0, b1);
            mma_f16(Cqk[2 * g + 1], af[s], b2, b3);
        }
    }
    const int t0 = wid * 16 + qr;
    const size_t qrowbase = (size_t)nb * 2048 + kt * 128;
    unsigned char* tile = g_tiles + (size_t)(nb * 16 + kt) * TILE_BYTES;
#pragma unroll
    for (int j = 0; j < 8; j++) {
        int col = j * 8 + qc * 2;
        float a0 = sA[col], c0 = sCc[col], a1 = sA[col + 1], c1v = sCc[col + 1];
        uint32_t u0 = pack_f16x2(Cqk[j][0] * a0 + c0, Cqk[j][1] * a1 + c1v);
        uint32_t u1 = pack_f16x2(Cqk[j][2] * a0 + c0, Cqk[j][3] * a1 + c1v);
        if (col < 32) {
            ((uint32_t*)g_qh)[(qrowbase + t0) * 16 + (col >> 1)]     = u0;
            ((uint32_t*)g_qh)[(qrowbase + t0 + 8) * 16 + (col >> 1)] = u1;
        } else {
            *(uint32_t*)(tile + t0 * 80 + (col - 32) * 2)       = u0;
            *(uint32_t*)(tile + (t0 + 8) * 80 + (col - 32) * 2) = u1;
        }
    }

    // ---- phase B: V^T = Wv x: [64cv x 64c] x [64c x 128px] ----
    const int mb4 = wid & 3, h2 = wid >> 2;
    uint32_t a2[4][4];
    const uint32_t a2base = (uint32_t)((64 + mb4 * 16 + (tsel & 1) * 8 + li) * 144 + (tsel >> 1) * 16);
#pragma unroll
    for (int s = 0; s < 4; s++)
        LDSM_X4(a2[s][0], a2[s][1], a2[s][2], a2[s][3], sbW + a2base + s * 32);

    float Cv[8][4];
#pragma unroll
    for (int j = 0; j < 8; j++)
#pragma unroll
        for (int k = 0; k < 4; k++) Cv[j][k] = 0.f;

#pragma unroll
    for (int g = 0; g < 4; g++) {
        const uint32_t b2base = (uint32_t)((h2 * 64 + g * 16 + (tsel >> 1) * 8 + li) * 144 + (tsel & 1) * 16);
#pragma unroll
        for (int s = 0; s < 4; s++) {
            uint32_t b0, b1, b2, b3;
            LDSM_X4(b0, b1, b2, b3, sbX + b2base + s * 32);
            mma_f16(Cv[2 * g],     a2[s], b0, b1);
            mma_f16(Cv[2 * g + 1], a2[s], b2, b3);
        }
    }
    const int cv0 = mb4 * 16 + qr;
    const float bv0 = sCc[64 + cv0], bv8 = sCc[64 + cv0 + 8];
#pragma unroll
    for (int j = 0; j < 8; j++) {
        int tcol = h2 * 64 + j * 8 + qc * 2;
        uint32_t u0 = pack_f16x2(Cv[j][0] + bv0, Cv[j][1] + bv0);
        uint32_t u1 = pack_f16x2(Cv[j][2] + bv8, Cv[j][3] + bv8);
        *(uint32_t*)(tile + BLOB_V + cv0 * 272 + tcol * 2)       = u0;
        *(uint32_t*)(tile + BLOB_V + (cv0 + 8) * 272 + tcol * 2) = u1;
    }
}

// ---------------------------------------------------------------- attention (R14 config; token order = (hl,side,wl))
#define OFF_Q    55296
#define OFF_MBAR 65536
#define SMEM_BYTES 65792
#define STG_PITCH 66

extern __shared__ char s_raw[];

__global__ __launch_bounds__(256, 2) void attn_kernel(float* __restrict__ out)
{
    const uint32_t sb = smem_u32(s_raw);
    float* stg = (float*)s_raw;

    const int tid = threadIdx.x;
    const int w   = tid >> 5;
    const int ln  = tid & 31;
    const int qr  = ln >> 2;
    const int qc  = ln & 3;
    const int nb    = blockIdx.y;
    const int chunk = blockIdx.x;
    const int qbase = chunk * 128;

    const int li   = ln & 7;
    const int tsel = ln >> 3;

    const uint32_t kbase = (uint32_t)(((tsel >> 1) * 8 + li) * 80 + (tsel & 1) * 16);
    const uint32_t vbase = (uint32_t)(((tsel >> 1) * 8 + li) * 272 + ((tsel & 1) * 8) * 2);
    const uint32_t qfrag = (uint32_t)((w * 16 + (tsel & 1) * 8 + li) * 80 + (tsel >> 1) * 16);

    const unsigned char* tiles = g_tiles + (size_t)nb * 16 * TILE_BYTES;

    if (tid == 0) {
        MBARRIER_INIT(sb + OFF_MBAR,     1);
        MBARRIER_INIT(sb + OFF_MBAR + 8, 1);
    }
    __syncthreads();
    if (tid == 0) {
        MBARRIER_EXPECT_TX(sb + OFF_MBAR, TILE_BYTES);
        CP_BULK(sb, tiles, TILE_BYTES, sb + OFF_MBAR);
    }
    for (int f = tid; f < 512; f += 256) {
        int row = f >> 2, j = f & 3;
        const size_t src = ((size_t)(nb * LSEQ + qbase + row)) * CKD + j * 8;
        *(uint4*)(s_raw + OFF_Q + row * 80 + j * 16) = *(const uint4*)(g_qh + src);
    }
    __syncthreads();

    uint32_t Qh[2][4];
#pragma unroll
    for (int s = 0; s < 2; s++)
        LDSM_X4(Qh[s][0], Qh[s][1], Qh[s][2], Qh[s][3], sb + OFF_Q + s * 32 + qfrag);

    float O[8][4];
#pragma unroll
    for (int v = 0; v < 8; v++)
#pragma unroll
        for (int j = 0; j < 4; j++) O[v][j] = 0.f;
    float rs0 = 0.f, rs1 = 0.f;

    for (int kt = 0; kt < 16; kt++) {
        MBARRIER_WAIT_PARITY(sb + OFF_MBAR + (kt & 1) * 8, (kt >> 1) & 1);
        __syncthreads();
        if (tid == 0 && kt < 15) {
            const uint32_t mbn = sb + OFF_MBAR + ((kt + 1) & 1) * 8;
            MBARRIER_EXPECT_TX(mbn, TILE_BYTES);
            CP_BULK(sb + ((kt + 1) & 1) * TILE_BYTES,
                    tiles + (size_t)(kt + 1) * TILE_BYTES, TILE_BYTES, mbn);
        }

        const uint32_t kB = sb + (kt & 1) * TILE_BYTES;
        const uint32_t vB = kB + BLOB_V;

#pragma unroll
        for (int t = 0; t < 8; t++) {
            float P0[4] = {0.f, 0.f, 0.f, 0.f};
            float P1[4] = {0.f, 0.f, 0.f, 0.f};
#pragma unroll
            for (int s = 0; s < 2; s++) {
                uint32_t kh[4];
                LDSM_X4(kh[0], kh[1], kh[2], kh[3], kB + t * 1280 + s * 32 + kbase);
                mma_f16(P0, Qh[s], kh[0], kh[1]);
                mma_f16(P1, Qh[s], kh[2], kh[3]);
            }

#pragma unroll
            for (int j = 0; j < 4; j++) { P0[j] = ex2(P0[j]); P1[j] = ex2(P1[j]); }
            rs0 += P0[0] + P0[1] + P1[0] + P1[1];
            rs1 += P0[2] + P0[3] + P1[2] + P1[3];

            uint32_t A[4];
            A[0] = pack_f16x2(P0[0], P0[1]);
            A[1] = pack_f16x2(P0[2], P0[3]);
            A[2] = pack_f16x2(P1[0], P1[1]);
            A[3] = pack_f16x2(P1[2], P1[3]);

#pragma unroll
            for (int i = 0; i < 4; i++) {
                const int vp = 2 * i;
                uint32_t vh[4];
                LDSM_X4(vh[0], vh[1], vh[2], vh[3], vB + vp * 2176 + t * 32 + vbase);
                mma_f16(O[vp],     A, vh[0], vh[1]);
                mma_f16(O[vp + 1], A, vh[2], vh[3]);
            }
        }
    }

    rs0 += __shfl_xor_sync(0xffffffffu, rs0, 1);
    rs0 += __shfl_xor_sync(0xffffffffu, rs0, 2);
    rs1 += __shfl_xor_sync(0xffffffffu, rs1, 1);
    rs1 += __shfl_xor_sync(0xffffffffu, rs1, 2);
    const float inv0 = 1.0f / rs0;
    const float inv1 = 1.0f / rs1;
    const int row0 = w * 16 + qr;

    __syncthreads();
#pragma unroll
    for (int v = 0; v < 8; v++) {
        int cv = v * 8 + qc * 2;
        *(float2*)&stg[(row0)     * STG_PITCH + cv] =
            make_float2(O[v][0] * inv0, O[v][1] * inv0);
        *(float2*)&stg[(row0 + 8) * STG_PITCH + cv] =
            make_float2(O[v][2] * inv1, O[v][3] * inv1);
    }
    __syncthreads();

    const int n = nb >> 2, b = nb & 3;
    const int bi = b >> 1, bj = b & 1;
    for (int e = tid; e < 8192; e += 256) {
        int wl   = e & 31;
        int side = (e >> 5) & 1;
        int hlo  = (e >> 6) & 1;
        int cv   = e >> 7;
        int ll   = hlo * 64 + side * 32 + wl;      // px-order token index
        int hh   = bi * 32 + chunk * 2 + hlo;
        int w2   = side * 64 + bj * 32 + wl;
        out[(((size_t)(n * 64 + cv)) * 64 + hh) * 128 + w2] = stg[ll * STG_PITCH + cv];
    }

    // re-zero mean banks for the next launch
    if (blockIdx.x == 0 && blockIdx.y == 0) {
        for (int i = tid; i < NBANK * 64; i += 256) g_sum[i] = 0.f;
    }
}

// ---------------------------------------------------------------- launch
extern "C" void kernel_launch(void* const* d_in, const int* in_sizes, int n_in,
                              void* d_out, int out_size)
{
    (void)in_sizes; (void)n_in; (void)out_size;
    const float* x     = (const float*)d_in[0];
    const float* Wq    = (const float*)d_in[1];
    const float* gq    = (const float*)d_in[3];
    const float* betaq = (const float*)d_in[4];
    const float* Wk    = (const float*)d_in[5];
    const float* gk    = (const float*)d_in[7];
    const float* betak = (const float*)d_in[8];
    const float* Wv    = (const float*)d_in[9];
    const float* bv    = (const float*)d_in[10];
    float* out = (float*)d_out;

    cudaFuncSetAttribute(attn_kernel, cudaFuncAttributeMaxDynamicSharedMemorySize,
                         SMEM_BYTES);

    cvt_kernel<<<128, 256>>>(x);
    cov_kernel<<<32, 256>>>();
    fold_kernel<<<1, 256>>>(Wq, Wk, Wv, gq, betaq, gk, betak, bv);
    convmma_kernel<<<dim3(16, 16), 256>>>();
    attn_kernel<<<dim3(16, 16), 256, SMEM_BYTES>>>(out);
}